// round 2
// baseline (speedup 1.0000x reference)
#include <cuda_runtime.h>
#include <math.h>

#define THREADS 128
#define ROWS_PER_THREAD 4
#define ROWS_PER_BLOCK (THREADS * ROWS_PER_THREAD)   // 512
#define F4_PER_BLOCK (ROWS_PER_BLOCK * 7 / 4)        // 896
#define SMEM_BYTES (2 * F4_PER_BLOCK * 16 + 64 * 4)  // 28928 < 48KB default

__global__ __launch_bounds__(THREADS)
void emotion_kernel(const float* __restrict__ rep,
                    const float* __restrict__ emo,
                    const float* __restrict__ WQ,
                    const float* __restrict__ WK,
                    const float* __restrict__ WD,
                    const float* __restrict__ bD,
                    float* __restrict__ out,
                    int nrows)
{
    extern __shared__ float4 sm4[];
    float4* sRep = sm4;                               // F4_PER_BLOCK entries
    float4* sEmo = sm4 + F4_PER_BLOCK;                // F4_PER_BLOCK entries
    float*  sM   = (float*)(sm4 + 2 * F4_PER_BLOCK);  // 56 floats (7x8 padded)
    float*  sCW  = sM + 56;                           // 8 floats: cw[0..6], [7]=sum(b_D)

    const int tid = threadIdx.x;

    // ---- per-block constant precompute (tiny; L2-cached loads) ----
    if (tid < 49) {
        int j = tid / 7, k = tid % 7;
        float acc = 0.f;
        #pragma unroll
        for (int i = 0; i < 7; ++i) acc = fmaf(WQ[i * 7 + j], WK[i * 7 + k], acc);
        sM[j * 8 + k] = acc;                          // M = W_Q^T @ W_K
    } else if (tid < 56) {
        int k = tid - 49;
        float acc = 0.f;
        #pragma unroll
        for (int j = 0; j < 7; ++j) acc += WD[j * 7 + k];
        sCW[k] = acc;                                 // colsum(W_D)
    } else if (tid == 56) {
        float acc = 0.f;
        #pragma unroll
        for (int i = 0; i < 7; ++i) acc += bD[i];
        sCW[7] = acc;                                 // sum(b_D)
    }

    // ---- coalesced stage-in: global float4 -> smem (linear, conflict-free) ----
    const long long base4  = (long long)blockIdx.x * F4_PER_BLOCK;
    const long long total4 = (long long)nrows * 7 / 4;
    const float4* grep = (const float4*)rep;
    const float4* gemo = (const float4*)emo;
    #pragma unroll
    for (int it = 0; it < 7; ++it) {
        int s = tid + it * THREADS;
        long long i = base4 + s;
        if (i < total4) {
            sRep[s] = grep[i];
            sEmo[s] = gemo[i];
        }
    }
    __syncthreads();

    // ---- per-thread loads: LDS.128 stride 112B (bank-conflict-free) ----
    float r[28], e[28], o[28];
    #pragma unroll
    for (int j = 0; j < 7; ++j) {
        float4 rv = sRep[tid * 7 + j];
        float4 ev = sEmo[tid * 7 + j];
        r[4 * j + 0] = rv.x; r[4 * j + 1] = rv.y; r[4 * j + 2] = rv.z; r[4 * j + 3] = rv.w;
        e[4 * j + 0] = ev.x; e[4 * j + 1] = ev.y; e[4 * j + 2] = ev.z; e[4 * j + 3] = ev.w;
    }

    float cw[7];
    #pragma unroll
    for (int k = 0; k < 7; ++k) cw[k] = sCW[k];
    const float cb = sCW[7];

    const long long row0 = (long long)blockIdx.x * ROWS_PER_BLOCK + (long long)tid * ROWS_PER_THREAD;

    #pragma unroll
    for (int rr = 0; rr < ROWS_PER_THREAD; ++rr) {
        if (row0 + rr < nrows) {
            // t = e_row @ M
            float t[7];
            #pragma unroll
            for (int k = 0; k < 7; ++k) t[k] = 0.f;
            #pragma unroll
            for (int j = 0; j < 7; ++j) {
                float ej = e[rr * 7 + j];
                #pragma unroll
                for (int k = 0; k < 7; ++k)
                    t[k] = fmaf(ej, sM[j * 8 + k], t[k]);
            }
            // raw = r * t ; softmax over 7
            float raw[7];
            float mx;
            #pragma unroll
            for (int k = 0; k < 7; ++k) raw[k] = r[rr * 7 + k] * t[k];
            mx = raw[0];
            #pragma unroll
            for (int k = 1; k < 7; ++k) mx = fmaxf(mx, raw[k]);
            float p[7], sum = 0.f;
            #pragma unroll
            for (int k = 0; k < 7; ++k) { p[k] = __expf(raw[k] - mx); sum += p[k]; }
            float inv = __fdividef(1.f, sum);
            // diff = clip(s^3 * cw + cb, -1, 1); out = r + diff
            #pragma unroll
            for (int k = 0; k < 7; ++k) {
                float s  = p[k] * inv;
                float s3 = s * s * s;
                float d  = fmaf(s3, cw[k], cb);
                d = fminf(1.f, fmaxf(-1.f, d));
                o[rr * 7 + k] = r[rr * 7 + k] + d;
            }
        } else {
            #pragma unroll
            for (int k = 0; k < 7; ++k) o[rr * 7 + k] = 0.f;
        }
    }

    // ---- write results back to own smem region (exclusive, no sync needed before) ----
    #pragma unroll
    for (int j = 0; j < 7; ++j) {
        float4 v;
        v.x = o[4 * j + 0]; v.y = o[4 * j + 1]; v.z = o[4 * j + 2]; v.w = o[4 * j + 3];
        sRep[tid * 7 + j] = v;
    }
    __syncthreads();

    // ---- coalesced stage-out ----
    float4* gout = (float4*)out;
    #pragma unroll
    for (int it = 0; it < 7; ++it) {
        int s = tid + it * THREADS;
        long long i = base4 + s;
        if (i < total4) gout[i] = sRep[s];
    }
}

extern "C" void kernel_launch(void* const* d_in, const int* in_sizes, int n_in,
                              void* d_out, int out_size)
{
    const float* rep = (const float*)d_in[0];
    const float* emo = (const float*)d_in[1];
    const float* WQ  = (const float*)d_in[2];
    const float* WK  = (const float*)d_in[3];
    const float* WD  = (const float*)d_in[4];
    const float* bD  = (const float*)d_in[5];
    float* out = (float*)d_out;

    int nrows = in_sizes[0] / 7;
    int grid  = (nrows + ROWS_PER_BLOCK - 1) / ROWS_PER_BLOCK;

    emotion_kernel<<<grid, THREADS, SMEM_BYTES>>>(rep, emo, WQ, WK, WD, bD, out, nrows);
}

// round 3
// speedup vs baseline: 1.1636x; 1.1636x over previous
#include <cuda_runtime.h>
#include <math.h>
#include <stdint.h>

#define THREADS 128
#define ROWS_PER_THREAD 4
#define ROWS_PER_BLOCK (THREADS * ROWS_PER_THREAD)     // 512
#define FLOATS_PER_BLOCK (ROWS_PER_BLOCK * 7)          // 3584
#define F4_PER_BLOCK (FLOATS_PER_BLOCK / 4)            // 896
#define BYTES_PER_BLOCK (FLOATS_PER_BLOCK * 4)         // 14336

__global__ __launch_bounds__(THREADS)
void emotion_kernel(const float* __restrict__ rep,
                    const float* __restrict__ emo,
                    const float* __restrict__ WQ,
                    const float* __restrict__ WK,
                    const float* __restrict__ WD,
                    const float* __restrict__ bD,
                    float* __restrict__ out,
                    int nrows)
{
    __shared__ __align__(16) float sRepF[FLOATS_PER_BLOCK];
    __shared__ __align__(16) float sEmoF[FLOATS_PER_BLOCK];
    __shared__ float sM[56];            // M = W_Q^T @ W_K, padded 7x8
    __shared__ float sCW[8];            // colsum(W_D)[0..6], [7] = sum(b_D)
    __shared__ __align__(8) unsigned long long mbar;

    const int tid = threadIdx.x;
    const long long row0blk = (long long)blockIdx.x * ROWS_PER_BLOCK;
    const bool fullblk = (row0blk + ROWS_PER_BLOCK) <= (long long)nrows;

    const uint32_t mbar_addr = (uint32_t)__cvta_generic_to_shared(&mbar);
    const uint32_t sRep_addr = (uint32_t)__cvta_generic_to_shared(sRepF);
    const uint32_t sEmo_addr = (uint32_t)__cvta_generic_to_shared(sEmoF);

    if (tid == 0) {
        asm volatile("mbarrier.init.shared::cta.b64 [%0], 1;" :: "r"(mbar_addr) : "memory");
    }
    __syncthreads();

    // ---- stage-in ----
    if (fullblk) {
        if (tid == 0) {
            asm volatile("mbarrier.arrive.expect_tx.shared::cta.b64 _, [%0], %1;"
                         :: "r"(mbar_addr), "r"(2 * BYTES_PER_BLOCK) : "memory");
            const float* grep = rep + row0blk * 7;
            const float* gemo = emo + row0blk * 7;
            asm volatile("cp.async.bulk.shared::cluster.global.mbarrier::complete_tx::bytes "
                         "[%0], [%1], %2, [%3];"
                         :: "r"(sRep_addr), "l"(grep), "r"(BYTES_PER_BLOCK), "r"(mbar_addr)
                         : "memory");
            asm volatile("cp.async.bulk.shared::cluster.global.mbarrier::complete_tx::bytes "
                         "[%0], [%1], %2, [%3];"
                         :: "r"(sEmo_addr), "l"(gemo), "r"(BYTES_PER_BLOCK), "r"(mbar_addr)
                         : "memory");
        }
    } else {
        // tail block: scalar fallback
        const long long total = (long long)nrows * 7;
        for (int s = tid; s < FLOATS_PER_BLOCK; s += THREADS) {
            long long i = row0blk * 7 + s;
            if (i < total) { sRepF[s] = rep[i]; sEmoF[s] = emo[i]; }
        }
    }

    // ---- per-block constant precompute (overlaps TMA) ----
    if (tid < 49) {
        int j = tid / 7, k = tid % 7;
        float acc = 0.f;
        #pragma unroll
        for (int i = 0; i < 7; ++i) acc = fmaf(WQ[i * 7 + j], WK[i * 7 + k], acc);
        sM[j * 8 + k] = acc;
    } else if (tid < 56) {
        int k = tid - 49;
        float acc = 0.f;
        #pragma unroll
        for (int j = 0; j < 7; ++j) acc += WD[j * 7 + k];
        sCW[k] = acc;
    } else if (tid == 56) {
        float acc = 0.f;
        #pragma unroll
        for (int i = 0; i < 7; ++i) acc += bD[i];
        sCW[7] = acc;
    }
    __syncthreads();   // constants + fallback staging visible

    if (fullblk) {
        // every thread waits for TMA completion (phase 0), acquire ordering
        asm volatile(
            "{\n\t"
            ".reg .pred P;\n\t"
            "WAIT_%=:\n\t"
            "mbarrier.try_wait.parity.acquire.cta.shared::cta.b64 P, [%0], 0;\n\t"
            "@!P bra WAIT_%=;\n\t"
            "}"
            :: "r"(mbar_addr) : "memory");
    }

    // ---- compute: per-thread 7 float4 loads (stride 112B, conflict-free) ----
    const float4* sRep4 = (const float4*)sRepF;
    const float4* sEmo4 = (const float4*)sEmoF;
    float r[28], e[28];
    #pragma unroll
    for (int j = 0; j < 7; ++j) {
        float4 rv = sRep4[tid * 7 + j];
        float4 ev = sEmo4[tid * 7 + j];
        r[4 * j + 0] = rv.x; r[4 * j + 1] = rv.y; r[4 * j + 2] = rv.z; r[4 * j + 3] = rv.w;
        e[4 * j + 0] = ev.x; e[4 * j + 1] = ev.y; e[4 * j + 2] = ev.z; e[4 * j + 3] = ev.w;
    }

    float cw[7];
    #pragma unroll
    for (int k = 0; k < 7; ++k) cw[k] = sCW[k];
    const float cb = sCW[7];

    const long long rowT = row0blk + (long long)tid * ROWS_PER_THREAD;

    #pragma unroll
    for (int rr = 0; rr < ROWS_PER_THREAD; ++rr) {
        if (rowT + rr < nrows) {
            float t[7];
            #pragma unroll
            for (int k = 0; k < 7; ++k) t[k] = 0.f;
            #pragma unroll
            for (int j = 0; j < 7; ++j) {
                float ej = e[rr * 7 + j];
                #pragma unroll
                for (int k = 0; k < 7; ++k)
                    t[k] = fmaf(ej, sM[j * 8 + k], t[k]);
            }
            float raw[7];
            #pragma unroll
            for (int k = 0; k < 7; ++k) raw[k] = r[rr * 7 + k] * t[k];
            float mx = raw[0];
            #pragma unroll
            for (int k = 1; k < 7; ++k) mx = fmaxf(mx, raw[k]);
            float p[7], sum = 0.f;
            #pragma unroll
            for (int k = 0; k < 7; ++k) { p[k] = __expf(raw[k] - mx); sum += p[k]; }
            float inv = __fdividef(1.f, sum);
            #pragma unroll
            for (int k = 0; k < 7; ++k) {
                float s  = p[k] * inv;
                float s3 = s * s * s;
                float d  = fmaf(s3, cw[k], cb);
                d = fminf(1.f, fmaxf(-1.f, d));
                r[rr * 7 + k] = r[rr * 7 + k] + d;   // in-place: out = r + diff
            }
        } else {
            #pragma unroll
            for (int k = 0; k < 7; ++k) r[rr * 7 + k] = 0.f;
        }
    }

    // ---- write results in place into own sRep region (exclusive per thread) ----
    float4* sOut4 = (float4*)sRepF;
    #pragma unroll
    for (int j = 0; j < 7; ++j) {
        float4 v;
        v.x = r[4 * j + 0]; v.y = r[4 * j + 1]; v.z = r[4 * j + 2]; v.w = r[4 * j + 3];
        sOut4[tid * 7 + j] = v;
    }

    // ---- stage-out ----
    if (fullblk) {
        asm volatile("fence.proxy.async.shared::cta;" ::: "memory");
        __syncthreads();
        if (tid == 0) {
            float* gdst = out + row0blk * 7;
            asm volatile("cp.async.bulk.global.shared::cta.bulk_group [%0], [%1], %2;"
                         :: "l"(gdst), "r"(sRep_addr), "r"(BYTES_PER_BLOCK) : "memory");
            asm volatile("cp.async.bulk.commit_group;" ::: "memory");
            asm volatile("cp.async.bulk.wait_group 0;" ::: "memory");
        }
    } else {
        __syncthreads();
        const long long total = (long long)nrows * 7;
        for (int s = tid; s < FLOATS_PER_BLOCK; s += THREADS) {
            long long i = row0blk * 7 + s;
            if (i < total) out[i] = sRepF[s];
        }
    }
}

extern "C" void kernel_launch(void* const* d_in, const int* in_sizes, int n_in,
                              void* d_out, int out_size)
{
    const float* rep = (const float*)d_in[0];
    const float* emo = (const float*)d_in[1];
    const float* WQ  = (const float*)d_in[2];
    const float* WK  = (const float*)d_in[3];
    const float* WD  = (const float*)d_in[4];
    const float* bD  = (const float*)d_in[5];
    float* out = (float*)d_out;

    int nrows = in_sizes[0] / 7;
    int grid  = (nrows + ROWS_PER_BLOCK - 1) / ROWS_PER_BLOCK;

    emotion_kernel<<<grid, THREADS>>>(rep, emo, WQ, WK, WD, bD, out, nrows);
}